// round 5
// baseline (speedup 1.0000x reference)
#include <cuda_runtime.h>

#define NN   3072
#define H    8
#define DH   32
#define HIDD 256
#define DEG  16
#define EDIM 32
#define FFND 1024
#define EE   (NN*DEG)

// ---------------- scratch (no allocations allowed) ----------------
__device__ float g_Q[NN*HIDD];
__device__ float g_K[NN*HIDD];
__device__ float g_V[NN*HIDD];
__device__ float g_attn[NN*HIDD];
__device__ float g_h1[NN*HIDD];
__device__ float g_ffn[NN*FFND];
__device__ float g_ea[H*EE];
__device__ float g_zero[HIDD];        // zero bias (device globals are zeroed)

// ---------------- tf32 helpers ----------------
__device__ __forceinline__ float to_tf32(float x) {
    unsigned u;
    asm("cvt.rna.tf32.f32 %0, %1;" : "=r"(u) : "f"(x));
    return __uint_as_float(u);
}
__device__ __forceinline__ void mma_tf32(float* c, const unsigned* a, const unsigned* b) {
    asm volatile(
        "mma.sync.aligned.m16n8k8.row.col.f32.tf32.tf32.f32 "
        "{%0,%1,%2,%3},{%4,%5,%6,%7},{%8,%9},{%0,%1,%2,%3};"
        : "+f"(c[0]), "+f"(c[1]), "+f"(c[2]), "+f"(c[3])
        : "r"(a[0]), "r"(a[1]), "r"(a[2]), "r"(a[3]), "r"(b[0]), "r"(b[1]));
}

constexpr int LA = 36;   // A smem pitch -> conflict-free frag LDS
constexpr int LB = 72;   // B smem pitch -> conflict-free frag LDS
constexpr int ASZ = 32 * LA;
constexpr int BSZ = 32 * LB;

// ---------------- tf32 GEMM body: 32x64 tile, 128 threads, double-buffered --
// 4 warps (2M x 2N), warp tile 16x32, K-chunk 32.
// NOTE: lda is the row stride of `in`; KTOT is only the K-extent consumed.
template<bool RELU>
__device__ __forceinline__ void gemm_body(
    const float* __restrict__ in,
    int lda,
    const float* __restrict__ W,
    const float* __restrict__ bias,
    float* __restrict__ out,
    int KTOT, int ldW, int r0, int cb0,
    float* As, float* Bs)
{
    const int tid  = threadIdx.x;
    const int warp = tid >> 5;
    const int lane = tid & 31;
    const int g    = lane >> 2;
    const int l    = lane & 3;
    const int wm   = warp & 1;        // warp row 0..1 (16 rows each)
    const int wn   = warp >> 1;       // warp col 0..1 (32 cols each)

    float c[4][4];
#pragma unroll
    for (int j = 0; j < 4; j++)
#pragma unroll
        for (int q = 0; q < 4; q++) c[j][q] = 0.f;

    const int am  = tid >> 2, ac4 = tid & 3;   // A: row am, col groups ac4, ac4+4
    const int bk  = tid >> 4, bc4 = tid & 15;  // B: rows bk+8i, col group bc4

    float4 av[2], bv[4];
    auto loadA = [&](int kc) {
        const float* p = in + (size_t)(r0 + am) * lda + kc;
        av[0] = *(const float4*)(p + ac4 * 4);
        av[1] = *(const float4*)(p + ac4 * 4 + 16);
    };
    auto loadB = [&](int kc) {
#pragma unroll
        for (int i = 0; i < 4; i++)
            bv[i] = *(const float4*)(W + (size_t)(kc + bk + 8 * i) * ldW + cb0 + bc4 * 4);
    };
    auto stage = [&](int st) {
        float* Ad = As + st * ASZ;
        float* Bd = Bs + st * BSZ;
        float4 t;
        t = av[0];
        *(float4*)&Ad[am * LA + ac4 * 4] =
            make_float4(to_tf32(t.x), to_tf32(t.y), to_tf32(t.z), to_tf32(t.w));
        t = av[1];
        *(float4*)&Ad[am * LA + ac4 * 4 + 16] =
            make_float4(to_tf32(t.x), to_tf32(t.y), to_tf32(t.z), to_tf32(t.w));
#pragma unroll
        for (int i = 0; i < 4; i++) {
            t = bv[i];
            *(float4*)&Bd[(bk + 8 * i) * LB + bc4 * 4] =
                make_float4(to_tf32(t.x), to_tf32(t.y), to_tf32(t.z), to_tf32(t.w));
        }
    };

    const int NC = KTOT >> 5;
    loadA(0); loadB(0);
    stage(0);

    for (int ch = 0; ch < NC; ch++) {
        if (ch + 1 < NC) { loadA((ch + 1) << 5); loadB((ch + 1) << 5); }
        __syncthreads();
        const float* Ac = As + (ch & 1) * ASZ;
        const float* Bc = Bs + (ch & 1) * BSZ;
#pragma unroll
        for (int ks = 0; ks < 4; ks++) {
            const int k0 = ks * 8;
            unsigned a[4];
            const int ar = wm * 16 + g;
            a[0] = __float_as_uint(Ac[ar * LA + k0 + l]);
            a[1] = __float_as_uint(Ac[(ar + 8) * LA + k0 + l]);
            a[2] = __float_as_uint(Ac[ar * LA + k0 + l + 4]);
            a[3] = __float_as_uint(Ac[(ar + 8) * LA + k0 + l + 4]);
#pragma unroll
            for (int j = 0; j < 4; j++) {
                unsigned b[2];
                const int bc = wn * 32 + j * 8 + g;
                b[0] = __float_as_uint(Bc[(k0 + l) * LB + bc]);
                b[1] = __float_as_uint(Bc[(k0 + l + 4) * LB + bc]);
                mma_tf32(c[j], a, b);
            }
        }
        if (ch + 1 < NC) stage((ch + 1) & 1);
    }

    const int row0 = r0 + wm * 16 + g;
#pragma unroll
    for (int j = 0; j < 4; j++) {
        const int col = cb0 + wn * 32 + j * 8 + l * 2;
        const float b0 = bias[col], b1 = bias[col + 1];
        float v00 = c[j][0] + b0, v01 = c[j][1] + b1;
        float v10 = c[j][2] + b0, v11 = c[j][3] + b1;
        if (RELU) {
            v00 = fmaxf(v00, 0.f); v01 = fmaxf(v01, 0.f);
            v10 = fmaxf(v10, 0.f); v11 = fmaxf(v11, 0.f);
        }
        *(float2*)&out[(size_t)row0 * ldW + col]       = make_float2(v00, v01);
        *(float2*)&out[(size_t)(row0 + 8) * ldW + col] = make_float2(v10, v11);
    }
}

template<bool RELU>
__global__ __launch_bounds__(128) void gemm_tc(
    const float* __restrict__ in, const float* __restrict__ W,
    const float* __restrict__ bias, float* __restrict__ out,
    int KTOT, int ldW)
{
    __shared__ float As[2 * ASZ];
    __shared__ float Bs[2 * BSZ];
    gemm_body<RELU>(in, KTOT, W, bias, out, KTOT, ldW,
                    blockIdx.x * 32, blockIdx.y * 64, As, Bs);
}

// fused QKV: blockIdx.y in [0,12): y>>2 selects matrix, y&3 selects col tile
__global__ __launch_bounds__(128) void gemm_qkv(
    const float* __restrict__ x,
    const float* __restrict__ Wq, const float* __restrict__ bq, float* __restrict__ oq,
    const float* __restrict__ Wk, const float* __restrict__ bk, float* __restrict__ ok,
    const float* __restrict__ Wv, const float* __restrict__ bv, float* __restrict__ ov)
{
    __shared__ float As[2 * ASZ];
    __shared__ float Bs[2 * BSZ];
    const int sel = blockIdx.y >> 2;
    const float* W = (sel == 0) ? Wq : (sel == 1) ? Wk : Wv;
    const float* b = (sel == 0) ? bq : (sel == 1) ? bk : bv;
    float*       o = (sel == 0) ? oq : (sel == 1) ? ok : ov;
    gemm_body<false>(x, HIDD, W, b, o, HIDD, HIDD,
                     blockIdx.x * 32, (blockIdx.y & 3) * 64, As, Bs);
}

// FFN-down, split-K=2: grid (96, 4, 2); z selects K-half and partial buffer.
// in rows have stride FFND (full ffn matrix), K-extent FFND/2 per half.
__global__ __launch_bounds__(128) void gemm_f2(
    const float* __restrict__ ffn, const float* __restrict__ Wf2,
    const float* __restrict__ zero,
    float* __restrict__ p0, float* __restrict__ p1)
{
    __shared__ float As[2 * ASZ];
    __shared__ float Bs[2 * BSZ];
    const int z = blockIdx.z;
    gemm_body<false>(ffn + z * (FFND / 2), FFND,
                     Wf2 + (size_t)z * (FFND / 2) * HIDD,
                     zero, z ? p1 : p0, FFND / 2, HIDD,
                     blockIdx.x * 32, blockIdx.y * 64, As, Bs);
}

// ---------------- edge bias: ea[h][e] = ef[e,:] @ We[:,h] + be[h] ----------
__global__ __launch_bounds__(256) void edge_kernel(
    const float* __restrict__ ef, const float* __restrict__ We,
    const float* __restrict__ be, float* __restrict__ ea)
{
    __shared__ float efs[32][33];
    __shared__ float Wes[256];
    const int tid = threadIdx.x;
    const int e0 = blockIdx.x * 32;
#pragma unroll
    for (int i = 0; i < 4; i++) {
        int lin = i * 256 + tid;
        efs[lin >> 5][lin & 31] = ef[(size_t)e0 * 32 + lin];
    }
    Wes[tid] = We[tid];
    __syncthreads();
    const int h = tid >> 5, el = tid & 31;
    float acc = be[h];
#pragma unroll
    for (int k = 0; k < 32; k++)
        acc = fmaf(efs[el][k], Wes[k * 8 + h], acc);
    ea[(size_t)h * EE + e0 + el] = acc;
}

// ---------------- attention: warp per (node, head) ----------------
__global__ __launch_bounds__(256) void attn2(
    const int*   __restrict__ neighbors,
    const float* __restrict__ ea,
    const float* __restrict__ Q,
    const float* __restrict__ K,
    const float* __restrict__ V,
    float* __restrict__ outp)
{
    const int n = blockIdx.x;
    const int h = threadIdx.x >> 5;
    const int lane = threadIdx.x & 31;
    const unsigned FULL = 0xffffffffu;

    __shared__ int s_nbr[DEG];
    __shared__ unsigned s_keep;

    if (h == 0) {
        int v = (lane < DEG) ? neighbors[n * DEG + lane] : -1;
        bool keep = (lane < DEG);
#pragma unroll
        for (int d2 = 1; d2 < DEG; d2++) {
            int other = __shfl_sync(FULL, v, d2);
            if (d2 > lane && other == v) keep = false;
        }
        unsigned km = __ballot_sync(FULL, keep && lane < DEG);
        if (lane < DEG) s_nbr[lane] = v;
        if (lane == 0) s_keep = km;
    }
    __syncthreads();

    const int nb_l = (lane < DEG) ? s_nbr[lane] : 0;
    const unsigned km = s_keep;
    const float q = Q[(size_t)n * HIDD + h * DH + lane];

    float kv[DEG];
#pragma unroll
    for (int d = 0; d < DEG; d++) {
        int s = __shfl_sync(FULL, nb_l, d);
        kv[d] = K[(size_t)s * HIDD + h * DH + lane];
    }
    float myscore = -1e30f;
#pragma unroll
    for (int d = 0; d < DEG; d++) {
        float p = q * kv[d];
#pragma unroll
        for (int o = 16; o; o >>= 1) p += __shfl_xor_sync(FULL, p, o);
        if (lane == d) myscore = p;
    }

    const bool keep = (lane < DEG) && ((km >> lane) & 1u);
    float bias = (lane < DEG) ? ea[(size_t)h * EE + n * DEG + lane] : 0.f;
    myscore = keep ? fmaf(myscore, 0.17677669529663687f, bias) : -1e30f;

    float m = myscore;
#pragma unroll
    for (int o = 16; o; o >>= 1) m = fmaxf(m, __shfl_xor_sync(FULL, m, o));
    float e = keep ? expf(myscore - m) : 0.f;
    float ssum = e;
#pragma unroll
    for (int o = 16; o; o >>= 1) ssum += __shfl_xor_sync(FULL, ssum, o);
    const float w = e / ssum;

    float vv[DEG];
#pragma unroll
    for (int d = 0; d < DEG; d++) {
        int s = __shfl_sync(FULL, nb_l, d);
        vv[d] = V[(size_t)s * HIDD + h * DH + lane];
    }
    float acc = 0.f;
#pragma unroll
    for (int d = 0; d < DEG; d++) {
        float wd = __shfl_sync(FULL, w, d);
        acc = fmaf(wd, vv[d], acc);
    }
    outp[(size_t)n * HIDD + h * DH + lane] = acc;
}

// ---------------- residual + LayerNorm (warp per row) ----------------
__global__ __launch_bounds__(256) void ln_res_kernel(
    const float* __restrict__ y, const float* __restrict__ res,
    const float* __restrict__ lg, const float* __restrict__ lb,
    float* __restrict__ out)
{
    const int warp = threadIdx.x >> 5, lane = threadIdx.x & 31;
    const int row = blockIdx.x * 8 + warp;
    const float4* yp = (const float4*)(y   + (size_t)row * HIDD);
    const float4* rp = (const float4*)(res + (size_t)row * HIDD);

    float4 v0 = yp[lane],      r0 = rp[lane];
    float4 v1 = yp[lane + 32], r1 = rp[lane + 32];
    v0.x += r0.x; v0.y += r0.y; v0.z += r0.z; v0.w += r0.w;
    v1.x += r1.x; v1.y += r1.y; v1.z += r1.z; v1.w += r1.w;

    float s  = v0.x + v0.y + v0.z + v0.w + v1.x + v1.y + v1.z + v1.w;
    float s2 = v0.x*v0.x + v0.y*v0.y + v0.z*v0.z + v0.w*v0.w
             + v1.x*v1.x + v1.y*v1.y + v1.z*v1.z + v1.w*v1.w;
#pragma unroll
    for (int o = 16; o; o >>= 1) {
        s  += __shfl_xor_sync(0xffffffffu, s,  o);
        s2 += __shfl_xor_sync(0xffffffffu, s2, o);
    }
    const float mu = s * (1.f / 256.f);
    const float var = fmaxf(s2 * (1.f / 256.f) - mu * mu, 0.f);
    const float rs = rsqrtf(var + 1e-5f);

    const float4* gp = (const float4*)lg;
    const float4* bp = (const float4*)lb;
    float4 g0 = gp[lane], g1 = gp[lane + 32];
    float4 b0 = bp[lane], b1 = bp[lane + 32];
    float4 o0, o1;
    o0.x = (v0.x - mu) * rs * g0.x + b0.x;  o0.y = (v0.y - mu) * rs * g0.y + b0.y;
    o0.z = (v0.z - mu) * rs * g0.z + b0.z;  o0.w = (v0.w - mu) * rs * g0.w + b0.w;
    o1.x = (v1.x - mu) * rs * g1.x + b1.x;  o1.y = (v1.y - mu) * rs * g1.y + b1.y;
    o1.z = (v1.z - mu) * rs * g1.z + b1.z;  o1.w = (v1.w - mu) * rs * g1.w + b1.w;
    ((float4*)(out + (size_t)row * HIDD))[lane]      = o0;
    ((float4*)(out + (size_t)row * HIDD))[lane + 32] = o1;
}

// split-K reduce + bias + residual + LayerNorm
__global__ __launch_bounds__(256) void ln_res3_kernel(
    const float* __restrict__ y0, const float* __restrict__ y1,
    const float* __restrict__ bias2,
    const float* __restrict__ res,
    const float* __restrict__ lg, const float* __restrict__ lb,
    float* __restrict__ out)
{
    const int warp = threadIdx.x >> 5, lane = threadIdx.x & 31;
    const int row = blockIdx.x * 8 + warp;
    const float4* y0p = (const float4*)(y0  + (size_t)row * HIDD);
    const float4* y1p = (const float4*)(y1  + (size_t)row * HIDD);
    const float4* rp  = (const float4*)(res + (size_t)row * HIDD);
    const float4* b2p = (const float4*)bias2;

    float4 v0 = y0p[lane],      v1 = y0p[lane + 32];
    float4 u0 = y1p[lane],      u1 = y1p[lane + 32];
    float4 r0 = rp[lane],       r1 = rp[lane + 32];
    float4 c0 = b2p[lane],      c1 = b2p[lane + 32];
    v0.x += u0.x + r0.x + c0.x; v0.y += u0.y + r0.y + c0.y;
    v0.z += u0.z + r0.z + c0.z; v0.w += u0.w + r0.w + c0.w;
    v1.x += u1.x + r1.x + c1.x; v1.y += u1.y + r1.y + c1.y;
    v1.z += u1.z + r1.z + c1.z; v1.w += u1.w + r1.w + c1.w;

    float s  = v0.x + v0.y + v0.z + v0.w + v1.x + v1.y + v1.z + v1.w;
    float s2 = v0.x*v0.x + v0.y*v0.y + v0.z*v0.z + v0.w*v0.w
             + v1.x*v1.x + v1.y*v1.y + v1.z*v1.z + v1.w*v1.w;
#pragma unroll
    for (int o = 16; o; o >>= 1) {
        s  += __shfl_xor_sync(0xffffffffu, s,  o);
        s2 += __shfl_xor_sync(0xffffffffu, s2, o);
    }
    const float mu = s * (1.f / 256.f);
    const float var = fmaxf(s2 * (1.f / 256.f) - mu * mu, 0.f);
    const float rs = rsqrtf(var + 1e-5f);

    const float4* gp = (const float4*)lg;
    const float4* bp = (const float4*)lb;
    float4 g0 = gp[lane], g1 = gp[lane + 32];
    float4 b0 = bp[lane], b1 = bp[lane + 32];
    float4 o0, o1;
    o0.x = (v0.x - mu) * rs * g0.x + b0.x;  o0.y = (v0.y - mu) * rs * g0.y + b0.y;
    o0.z = (v0.z - mu) * rs * g0.z + b0.z;  o0.w = (v0.w - mu) * rs * g0.w + b0.w;
    o1.x = (v1.x - mu) * rs * g1.x + b1.x;  o1.y = (v1.y - mu) * rs * g1.y + b1.y;
    o1.z = (v1.z - mu) * rs * g1.z + b1.z;  o1.w = (v1.w - mu) * rs * g1.w + b1.w;
    ((float4*)(out + (size_t)row * HIDD))[lane]      = o0;
    ((float4*)(out + (size_t)row * HIDD))[lane + 32] = o1;
}

// ---------------- launch ----------------
extern "C" void kernel_launch(void* const* d_in, const int* in_sizes, int n_in,
                              void* d_out, int out_size)
{
    const float* x    = (const float*)d_in[0];
    const int*   nb   = (const int*)  d_in[1];
    const float* ef   = (const float*)d_in[2];
    const float* Wq   = (const float*)d_in[3];
    const float* bq   = (const float*)d_in[4];
    const float* Wk   = (const float*)d_in[5];
    const float* bk   = (const float*)d_in[6];
    const float* Wv   = (const float*)d_in[7];
    const float* bv   = (const float*)d_in[8];
    const float* We   = (const float*)d_in[9];
    const float* be   = (const float*)d_in[10];
    const float* Wo   = (const float*)d_in[11];
    const float* bo   = (const float*)d_in[12];
    const float* ln1g = (const float*)d_in[13];
    const float* ln1b = (const float*)d_in[14];
    const float* ln2g = (const float*)d_in[15];
    const float* ln2b = (const float*)d_in[16];
    const float* Wf1  = (const float*)d_in[17];
    const float* bf1  = (const float*)d_in[18];
    const float* Wf2  = (const float*)d_in[19];
    const float* bf2  = (const float*)d_in[20];
    float* out = (float*)d_out;

    float *pQ, *pK, *pV, *pA, *pH1, *pF, *pEA, *pZ;
    cudaGetSymbolAddress((void**)&pQ,  g_Q);
    cudaGetSymbolAddress((void**)&pK,  g_K);
    cudaGetSymbolAddress((void**)&pV,  g_V);
    cudaGetSymbolAddress((void**)&pA,  g_attn);
    cudaGetSymbolAddress((void**)&pH1, g_h1);
    cudaGetSymbolAddress((void**)&pF,  g_ffn);
    cudaGetSymbolAddress((void**)&pEA, g_ea);
    cudaGetSymbolAddress((void**)&pZ,  g_zero);

    // edge bias projection (be folded into ea here)
    edge_kernel<<<EE / 32, 256>>>(ef, We, be, pEA);

    // fused QKV projection
    gemm_qkv<<<dim3(NN / 32, 12), 128>>>(x, Wq, bq, pQ, Wk, bk, pK, Wv, bv, pV);

    // sparse attention
    attn2<<<NN, 256>>>(nb, pEA, pQ, pK, pV, pA);

    // Wo, then residual + LN1 -> h1
    gemm_tc<false><<<dim3(NN / 32, HIDD / 64), 128>>>(pA, Wo, bo, pK, HIDD, HIDD);
    ln_res_kernel<<<NN / 8, 256>>>(pK, x, ln1g, ln1b, pH1);

    // FFN up + ReLU
    gemm_tc<true><<<dim3(NN / 32, FFND / 64), 128>>>(pH1, Wf1, bf1, pF, HIDD, FFND);

    // FFN down, split-K=2 -> partials pQ, pA; reduce + bias + residual + LN2
    gemm_f2<<<dim3(NN / 32, HIDD / 64, 2), 128>>>(pF, Wf2, pZ, pQ, pA);
    ln_res3_kernel<<<NN / 8, 256>>>(pQ, pA, bf2, pH1, ln2g, ln2b, out);
}

// round 6
// speedup vs baseline: 1.1135x; 1.1135x over previous
#include <cuda_runtime.h>

#define NN   3072
#define H    8
#define DH   32
#define HIDD 256
#define DEG  16
#define EDIM 32
#define FFND 1024
#define EE   (NN*DEG)

// ---------------- scratch (no allocations allowed) ----------------
__device__ float g_Q[NN*HIDD];
__device__ float g_K[NN*HIDD];
__device__ float g_V[NN*HIDD];
__device__ float g_attn[NN*HIDD];
__device__ float g_h1[NN*HIDD];
__device__ float g_ffn[NN*FFND];
__device__ float g_zero[HIDD];        // zero bias (device globals are zeroed)

// ---------------- tf32 helpers ----------------
__device__ __forceinline__ float to_tf32(float x) {
    unsigned u;
    asm("cvt.rna.tf32.f32 %0, %1;" : "=r"(u) : "f"(x));
    return __uint_as_float(u);
}
__device__ __forceinline__ void mma_tf32(float* c, const unsigned* a, const unsigned* b) {
    asm volatile(
        "mma.sync.aligned.m16n8k8.row.col.f32.tf32.tf32.f32 "
        "{%0,%1,%2,%3},{%4,%5,%6,%7},{%8,%9},{%0,%1,%2,%3};"
        : "+f"(c[0]), "+f"(c[1]), "+f"(c[2]), "+f"(c[3])
        : "r"(a[0]), "r"(a[1]), "r"(a[2]), "r"(a[3]), "r"(b[0]), "r"(b[1]));
}

constexpr int LA = 36;   // A smem pitch -> conflict-free frag LDS
constexpr int LB = 72;   // B smem pitch -> conflict-free frag LDS
constexpr int ASZ = 64 * LA;
constexpr int BSZ = 32 * LB;

// ---------------- tf32 GEMM body: 64x64 tile, 256 threads, double-buffered -
// 8 warps (4M x 2N), warp tile 16x32, K-chunk 32, 1 sync per chunk.
// lda = row stride of `in`; KTOT = K-extent consumed.
template<bool RELU>
__device__ __forceinline__ void gemm_body(
    const float* __restrict__ in, int lda,
    const float* __restrict__ W,
    const float* __restrict__ bias,
    float* __restrict__ out,
    int KTOT, int ldW, int r0, int cb0,
    float* As, float* Bs)
{
    const int tid  = threadIdx.x;
    const int warp = tid >> 5;
    const int lane = tid & 31;
    const int g    = lane >> 2;
    const int l    = lane & 3;
    const int wm   = warp & 3;
    const int wn   = warp >> 2;

    float c[4][4];
#pragma unroll
    for (int j = 0; j < 4; j++)
#pragma unroll
        for (int q = 0; q < 4; q++) c[j][q] = 0.f;

    const int am = tid >> 3, ac4 = tid & 7;     // A rows am, am+32; col group ac4
    const int bk = tid >> 4, bc4 = tid & 15;    // B rows bk, bk+16; col group bc4

    float4 av[2], bv[2];
    auto loadA = [&](int kc) {
        av[0] = *(const float4*)(in + (size_t)(r0 + am)      * lda + kc + ac4 * 4);
        av[1] = *(const float4*)(in + (size_t)(r0 + am + 32) * lda + kc + ac4 * 4);
    };
    auto loadB = [&](int kc) {
        bv[0] = *(const float4*)(W + (size_t)(kc + bk)      * ldW + cb0 + bc4 * 4);
        bv[1] = *(const float4*)(W + (size_t)(kc + bk + 16) * ldW + cb0 + bc4 * 4);
    };
    auto stage = [&](int st) {
        float* Ad = As + st * ASZ;
        float* Bd = Bs + st * BSZ;
        float4 t;
        t = av[0];
        *(float4*)&Ad[am * LA + ac4 * 4] =
            make_float4(to_tf32(t.x), to_tf32(t.y), to_tf32(t.z), to_tf32(t.w));
        t = av[1];
        *(float4*)&Ad[(am + 32) * LA + ac4 * 4] =
            make_float4(to_tf32(t.x), to_tf32(t.y), to_tf32(t.z), to_tf32(t.w));
        t = bv[0];
        *(float4*)&Bd[bk * LB + bc4 * 4] =
            make_float4(to_tf32(t.x), to_tf32(t.y), to_tf32(t.z), to_tf32(t.w));
        t = bv[1];
        *(float4*)&Bd[(bk + 16) * LB + bc4 * 4] =
            make_float4(to_tf32(t.x), to_tf32(t.y), to_tf32(t.z), to_tf32(t.w));
    };

    const int NC = KTOT >> 5;
    loadA(0); loadB(0);
    stage(0);

    for (int ch = 0; ch < NC; ch++) {
        if (ch + 1 < NC) { loadA((ch + 1) << 5); loadB((ch + 1) << 5); }
        __syncthreads();
        const float* Ac = As + (ch & 1) * ASZ;
        const float* Bc = Bs + (ch & 1) * BSZ;
#pragma unroll
        for (int ks = 0; ks < 4; ks++) {
            const int k0 = ks * 8;
            unsigned a[4];
            const int ar = wm * 16 + g;
            a[0] = __float_as_uint(Ac[ar * LA + k0 + l]);
            a[1] = __float_as_uint(Ac[(ar + 8) * LA + k0 + l]);
            a[2] = __float_as_uint(Ac[ar * LA + k0 + l + 4]);
            a[3] = __float_as_uint(Ac[(ar + 8) * LA + k0 + l + 4]);
#pragma unroll
            for (int j = 0; j < 4; j++) {
                unsigned b[2];
                const int bc = wn * 32 + j * 8 + g;
                b[0] = __float_as_uint(Bc[(k0 + l) * LB + bc]);
                b[1] = __float_as_uint(Bc[(k0 + l + 4) * LB + bc]);
                mma_tf32(c[j], a, b);
            }
        }
        if (ch + 1 < NC) stage((ch + 1) & 1);
    }

    const int row0 = r0 + wm * 16 + g;
#pragma unroll
    for (int j = 0; j < 4; j++) {
        const int col = cb0 + wn * 32 + j * 8 + l * 2;
        const float b0 = bias[col], b1 = bias[col + 1];
        float v00 = c[j][0] + b0, v01 = c[j][1] + b1;
        float v10 = c[j][2] + b0, v11 = c[j][3] + b1;
        if (RELU) {
            v00 = fmaxf(v00, 0.f); v01 = fmaxf(v01, 0.f);
            v10 = fmaxf(v10, 0.f); v11 = fmaxf(v11, 0.f);
        }
        *(float2*)&out[(size_t)row0 * ldW + col]       = make_float2(v00, v01);
        *(float2*)&out[(size_t)(row0 + 8) * ldW + col] = make_float2(v10, v11);
    }
}

template<bool RELU>
__global__ __launch_bounds__(256) void gemm_tc(
    const float* __restrict__ in, const float* __restrict__ W,
    const float* __restrict__ bias, float* __restrict__ out,
    int KTOT, int ldW)
{
    __shared__ float As[2 * ASZ];
    __shared__ float Bs[2 * BSZ];
    gemm_body<RELU>(in, KTOT, W, bias, out, KTOT, ldW,
                    blockIdx.x * 64, blockIdx.y * 64, As, Bs);
}

// fused QKV: blockIdx.y in [0,12)
__global__ __launch_bounds__(256) void gemm_qkv(
    const float* __restrict__ x,
    const float* __restrict__ Wq, const float* __restrict__ bq, float* __restrict__ oq,
    const float* __restrict__ Wk, const float* __restrict__ bk, float* __restrict__ ok,
    const float* __restrict__ Wv, const float* __restrict__ bv, float* __restrict__ ov)
{
    __shared__ float As[2 * ASZ];
    __shared__ float Bs[2 * BSZ];
    const int sel = blockIdx.y >> 2;
    const float* W = (sel == 0) ? Wq : (sel == 1) ? Wk : Wv;
    const float* b = (sel == 0) ? bq : (sel == 1) ? bk : bv;
    float*       o = (sel == 0) ? oq : (sel == 1) ? ok : ov;
    gemm_body<false>(x, HIDD, W, b, o, HIDD, HIDD,
                     blockIdx.x * 64, (blockIdx.y & 3) * 64, As, Bs);
}

// Wo, split-K=2: grid (48, 4, 2). K=128 per split, lda=HIDD.
__global__ __launch_bounds__(256) void gemm_wo(
    const float* __restrict__ in, const float* __restrict__ Wo,
    const float* __restrict__ zero,
    float* __restrict__ p0, float* __restrict__ p1)
{
    __shared__ float As[2 * ASZ];
    __shared__ float Bs[2 * BSZ];
    const int z = blockIdx.z;
    gemm_body<false>(in + z * (HIDD / 2), HIDD,
                     Wo + (size_t)z * (HIDD / 2) * HIDD,
                     zero, z ? p1 : p0, HIDD / 2, HIDD,
                     blockIdx.x * 64, blockIdx.y * 64, As, Bs);
}

// FFN-down, split-K=4: grid (48, 4, 4). K=256 per split, lda=FFND.
__global__ __launch_bounds__(256) void gemm_f2(
    const float* __restrict__ ffn, const float* __restrict__ Wf2,
    const float* __restrict__ zero,
    float* __restrict__ p0, float* __restrict__ p1,
    float* __restrict__ p2, float* __restrict__ p3)
{
    __shared__ float As[2 * ASZ];
    __shared__ float Bs[2 * BSZ];
    const int z = blockIdx.z;
    float* p = (z == 0) ? p0 : (z == 1) ? p1 : (z == 2) ? p2 : p3;
    gemm_body<false>(ffn + z * (FFND / 4), FFND,
                     Wf2 + (size_t)z * (FFND / 4) * HIDD,
                     zero, p, FFND / 4, HIDD,
                     blockIdx.x * 64, blockIdx.y * 64, As, Bs);
}

// ---------------- attention: warp per (node, head), fused edge bias -------
__global__ __launch_bounds__(256) void attn2(
    const int*   __restrict__ neighbors,
    const float* __restrict__ ef,     // [E, 32]
    const float* __restrict__ We,     // [32, 8]
    const float* __restrict__ be,     // [8]
    const float* __restrict__ Q,
    const float* __restrict__ K,
    const float* __restrict__ V,
    float* __restrict__ outp)
{
    const int n = blockIdx.x;
    const int h = threadIdx.x >> 5;
    const int lane = threadIdx.x & 31;
    const int tid = threadIdx.x;
    const unsigned FULL = 0xffffffffu;

    __shared__ float efs[DEG][33];    // 16 edges x 32 dims, padded
    __shared__ float Wes[256];
    __shared__ int s_nbr[DEG];
    __shared__ unsigned s_keep;

    // load edge features for this node's 16 edges (512 floats) + We (256)
    {
        const float* eb = ef + (size_t)n * DEG * EDIM;
#pragma unroll
        for (int i = 0; i < 2; i++) {
            int lin = tid + i * 256;
            efs[lin >> 5][lin & 31] = eb[lin];
        }
        Wes[tid] = We[tid];
    }
    if (h == 0) {
        int v = (lane < DEG) ? neighbors[n * DEG + lane] : -1;
        bool keep = (lane < DEG);
#pragma unroll
        for (int d2 = 1; d2 < DEG; d2++) {
            int other = __shfl_sync(FULL, v, d2);
            if (d2 > lane && other == v) keep = false;
        }
        unsigned km = __ballot_sync(FULL, keep && lane < DEG);
        if (lane < DEG) s_nbr[lane] = v;
        if (lane == 0) s_keep = km;
    }
    __syncthreads();

    const int nb_l = (lane < DEG) ? s_nbr[lane] : 0;
    const unsigned km = s_keep;
    const float q = Q[(size_t)n * HIDD + h * DH + lane];

    // edge bias for lane's edge: ef[n*16+lane,:] . We[:,h] + be[h]
    float bias = be[h];
    if (lane < DEG) {
#pragma unroll
        for (int k = 0; k < EDIM; k++)
            bias = fmaf(efs[lane][k], Wes[k * 8 + h], bias);
    }

    float kv[DEG];
#pragma unroll
    for (int d = 0; d < DEG; d++) {
        int s = __shfl_sync(FULL, nb_l, d);
        kv[d] = K[(size_t)s * HIDD + h * DH + lane];
    }
    float myscore = -1e30f;
#pragma unroll
    for (int d = 0; d < DEG; d++) {
        float p = q * kv[d];
#pragma unroll
        for (int o = 16; o; o >>= 1) p += __shfl_xor_sync(FULL, p, o);
        if (lane == d) myscore = p;
    }

    const bool keep = (lane < DEG) && ((km >> lane) & 1u);
    myscore = keep ? fmaf(myscore, 0.17677669529663687f, bias) : -1e30f;

    float m = myscore;
#pragma unroll
    for (int o = 16; o; o >>= 1) m = fmaxf(m, __shfl_xor_sync(FULL, m, o));
    float e = keep ? expf(myscore - m) : 0.f;
    float ssum = e;
#pragma unroll
    for (int o = 16; o; o >>= 1) ssum += __shfl_xor_sync(FULL, ssum, o);
    const float w = e / ssum;

    float vv[DEG];
#pragma unroll
    for (int d = 0; d < DEG; d++) {
        int s = __shfl_sync(FULL, nb_l, d);
        vv[d] = V[(size_t)s * HIDD + h * DH + lane];
    }
    float acc = 0.f;
#pragma unroll
    for (int d = 0; d < DEG; d++) {
        float wd = __shfl_sync(FULL, w, d);
        acc = fmaf(wd, vv[d], acc);
    }
    outp[(size_t)n * HIDD + h * DH + lane] = acc;
}

// ---------------- 2-partial reduce + bias + residual + LayerNorm ----------
__global__ __launch_bounds__(256) void ln_res3_kernel(
    const float* __restrict__ y0, const float* __restrict__ y1,
    const float* __restrict__ bias2,
    const float* __restrict__ res,
    const float* __restrict__ lg, const float* __restrict__ lb,
    float* __restrict__ out)
{
    const int warp = threadIdx.x >> 5, lane = threadIdx.x & 31;
    const int row = blockIdx.x * 8 + warp;
    const float4* y0p = (const float4*)(y0  + (size_t)row * HIDD);
    const float4* y1p = (const float4*)(y1  + (size_t)row * HIDD);
    const float4* rp  = (const float4*)(res + (size_t)row * HIDD);
    const float4* b2p = (const float4*)bias2;

    float4 v0 = y0p[lane],      v1 = y0p[lane + 32];
    float4 u0 = y1p[lane],      u1 = y1p[lane + 32];
    float4 r0 = rp[lane],       r1 = rp[lane + 32];
    float4 c0 = b2p[lane],      c1 = b2p[lane + 32];
    v0.x += u0.x + r0.x + c0.x; v0.y += u0.y + r0.y + c0.y;
    v0.z += u0.z + r0.z + c0.z; v0.w += u0.w + r0.w + c0.w;
    v1.x += u1.x + r1.x + c1.x; v1.y += u1.y + r1.y + c1.y;
    v1.z += u1.z + r1.z + c1.z; v1.w += u1.w + r1.w + c1.w;

    float s  = v0.x + v0.y + v0.z + v0.w + v1.x + v1.y + v1.z + v1.w;
    float s2 = v0.x*v0.x + v0.y*v0.y + v0.z*v0.z + v0.w*v0.w
             + v1.x*v1.x + v1.y*v1.y + v1.z*v1.z + v1.w*v1.w;
#pragma unroll
    for (int o = 16; o; o >>= 1) {
        s  += __shfl_xor_sync(0xffffffffu, s,  o);
        s2 += __shfl_xor_sync(0xffffffffu, s2, o);
    }
    const float mu = s * (1.f / 256.f);
    const float var = fmaxf(s2 * (1.f / 256.f) - mu * mu, 0.f);
    const float rs = rsqrtf(var + 1e-5f);

    const float4* gp = (const float4*)lg;
    const float4* bp = (const float4*)lb;
    float4 g0 = gp[lane], g1 = gp[lane + 32];
    float4 b0 = bp[lane], b1 = bp[lane + 32];
    float4 o0, o1;
    o0.x = (v0.x - mu) * rs * g0.x + b0.x;  o0.y = (v0.y - mu) * rs * g0.y + b0.y;
    o0.z = (v0.z - mu) * rs * g0.z + b0.z;  o0.w = (v0.w - mu) * rs * g0.w + b0.w;
    o1.x = (v1.x - mu) * rs * g1.x + b1.x;  o1.y = (v1.y - mu) * rs * g1.y + b1.y;
    o1.z = (v1.z - mu) * rs * g1.z + b1.z;  o1.w = (v1.w - mu) * rs * g1.w + b1.w;
    ((float4*)(out + (size_t)row * HIDD))[lane]      = o0;
    ((float4*)(out + (size_t)row * HIDD))[lane + 32] = o1;
}

// ---------------- 4-partial reduce + bias + residual + LayerNorm ----------
__global__ __launch_bounds__(256) void ln_res4_kernel(
    const float* __restrict__ y0, const float* __restrict__ y1,
    const float* __restrict__ y2, const float* __restrict__ y3,
    const float* __restrict__ bias2,
    const float* __restrict__ res,
    const float* __restrict__ lg, const float* __restrict__ lb,
    float* __restrict__ out)
{
    const int warp = threadIdx.x >> 5, lane = threadIdx.x & 31;
    const int row = blockIdx.x * 8 + warp;
    const size_t off = (size_t)row * HIDD;
    const float4* y0p = (const float4*)(y0 + off);
    const float4* y1p = (const float4*)(y1 + off);
    const float4* y2p = (const float4*)(y2 + off);
    const float4* y3p = (const float4*)(y3 + off);
    const float4* rp  = (const float4*)(res + off);
    const float4* b2p = (const float4*)bias2;

    float4 v0, v1;
#pragma unroll
    for (int half = 0; half < 1; half++) {} // (keep structure simple)
    {
        float4 a0 = y0p[lane], a1 = y1p[lane], a2 = y2p[lane], a3 = y3p[lane];
        float4 r0 = rp[lane],  c0 = b2p[lane];
        v0.x = a0.x + a1.x + a2.x + a3.x + r0.x + c0.x;
        v0.y = a0.y + a1.y + a2.y + a3.y + r0.y + c0.y;
        v0.z = a0.z + a1.z + a2.z + a3.z + r0.z + c0.z;
        v0.w = a0.w + a1.w + a2.w + a3.w + r0.w + c0.w;
    }
    {
        float4 a0 = y0p[lane+32], a1 = y1p[lane+32], a2 = y2p[lane+32], a3 = y3p[lane+32];
        float4 r1 = rp[lane+32],  c1 = b2p[lane+32];
        v1.x = a0.x + a1.x + a2.x + a3.x + r1.x + c1.x;
        v1.y = a0.y + a1.y + a2.y + a3.y + r1.y + c1.y;
        v1.z = a0.z + a1.z + a2.z + a3.z + r1.z + c1.z;
        v1.w = a0.w + a1.w + a2.w + a3.w + r1.w + c1.w;
    }

    float s  = v0.x + v0.y + v0.z + v0.w + v1.x + v1.y + v1.z + v1.w;
    float s2 = v0.x*v0.x + v0.y*v0.y + v0.z*v0.z + v0.w*v0.w
             + v1.x*v1.x + v1.y*v1.y + v1.z*v1.z + v1.w*v1.w;
#pragma unroll
    for (int o = 16; o; o >>= 1) {
        s  += __shfl_xor_sync(0xffffffffu, s,  o);
        s2 += __shfl_xor_sync(0xffffffffu, s2, o);
    }
    const float mu = s * (1.f / 256.f);
    const float var = fmaxf(s2 * (1.f / 256.f) - mu * mu, 0.f);
    const float rs = rsqrtf(var + 1e-5f);

    const float4* gp = (const float4*)lg;
    const float4* bp = (const float4*)lb;
    float4 g0 = gp[lane], g1 = gp[lane + 32];
    float4 b0 = bp[lane], b1 = bp[lane + 32];
    float4 o0, o1;
    o0.x = (v0.x - mu) * rs * g0.x + b0.x;  o0.y = (v0.y - mu) * rs * g0.y + b0.y;
    o0.z = (v0.z - mu) * rs * g0.z + b0.z;  o0.w = (v0.w - mu) * rs * g0.w + b0.w;
    o1.x = (v1.x - mu) * rs * g1.x + b1.x;  o1.y = (v1.y - mu) * rs * g1.y + b1.y;
    o1.z = (v1.z - mu) * rs * g1.z + b1.z;  o1.w = (v1.w - mu) * rs * g1.w + b1.w;
    ((float4*)(out + off))[lane]      = o0;
    ((float4*)(out + off))[lane + 32] = o1;
}

// ---------------- launch ----------------
extern "C" void kernel_launch(void* const* d_in, const int* in_sizes, int n_in,
                              void* d_out, int out_size)
{
    const float* x    = (const float*)d_in[0];
    const int*   nb   = (const int*)  d_in[1];
    const float* ef   = (const float*)d_in[2];
    const float* Wq   = (const float*)d_in[3];
    const float* bq   = (const float*)d_in[4];
    const float* Wk   = (const float*)d_in[5];
    const float* bk   = (const float*)d_in[6];
    const float* Wv   = (const float*)d_in[7];
    const float* bv   = (const float*)d_in[8];
    const float* We   = (const float*)d_in[9];
    const float* be   = (const float*)d_in[10];
    const float* Wo   = (const float*)d_in[11];
    const float* bo   = (const float*)d_in[12];
    const float* ln1g = (const float*)d_in[13];
    const float* ln1b = (const float*)d_in[14];
    const float* ln2g = (const float*)d_in[15];
    const float* ln2b = (const float*)d_in[16];
    const float* Wf1  = (const float*)d_in[17];
    const float* bf1  = (const float*)d_in[18];
    const float* Wf2  = (const float*)d_in[19];
    const float* bf2  = (const float*)d_in[20];
    float* out = (float*)d_out;

    float *pQ, *pK, *pV, *pA, *pH1, *pF, *pZ;
    cudaGetSymbolAddress((void**)&pQ,  g_Q);
    cudaGetSymbolAddress((void**)&pK,  g_K);
    cudaGetSymbolAddress((void**)&pV,  g_V);
    cudaGetSymbolAddress((void**)&pA,  g_attn);
    cudaGetSymbolAddress((void**)&pH1, g_h1);
    cudaGetSymbolAddress((void**)&pF,  g_ffn);
    cudaGetSymbolAddress((void**)&pZ,  g_zero);

    // fused QKV projection
    gemm_qkv<<<dim3(NN / 64, 12), 256>>>(x, Wq, bq, pQ, Wk, bk, pK, Wv, bv, pV);

    // sparse attention with fused edge-bias projection
    attn2<<<NN, 256>>>(nb, ef, We, be, pQ, pK, pV, pA);

    // Wo split-K=2 -> partials pQ, pK; reduce + bo + residual(x) + LN1 -> h1
    gemm_wo<<<dim3(NN / 64, HIDD / 64, 2), 256>>>(pA, Wo, pZ, pQ, pK);
    ln_res3_kernel<<<NN / 8, 256>>>(pQ, pK, bo, x, ln1g, ln1b, pH1);

    // FFN up + ReLU
    gemm_tc<true><<<dim3(NN / 64, FFND / 64), 256>>>(pH1, Wf1, bf1, pF, HIDD, FFND);

    // FFN down split-K=4 -> partials pQ,pK,pV,pA; reduce + bf2 + res(h1) + LN2
    gemm_f2<<<dim3(NN / 64, HIDD / 64, 4), 256>>>(pF, Wf2, pZ, pQ, pK, pV, pA);
    ln_res4_kernel<<<NN / 8, 256>>>(pQ, pK, pV, pA, bf2, pH1, ln2g, ln2b, out);
}

// round 9
// speedup vs baseline: 1.1803x; 1.0600x over previous
#include <cuda_runtime.h>

#define NN   3072
#define H    8
#define DH   32
#define HIDD 256
#define DEG  16
#define EDIM 32
#define FFND 1024
#define EE   (NN*DEG)

// ---------------- scratch (no allocations allowed) ----------------
__device__ float g_Q[NN*HIDD];
__device__ float g_K[NN*HIDD];
__device__ float g_V[NN*HIDD];
__device__ float g_attn[NN*HIDD];
__device__ float g_h1[NN*HIDD];
__device__ float g_h1t[NN*HIDD];      // tf32-rounded h1 (A operand of f1)
__device__ float g_ffn[NN*FFND];
__device__ float g_zero[HIDD];        // zero bias (device globals are zeroed)
// tf32-rounded operands
__device__ float g_xt[NN*HIDD];
__device__ float g_Wqt[HIDD*HIDD];
__device__ float g_Wkt[HIDD*HIDD];
__device__ float g_Wvt[HIDD*HIDD];
__device__ float g_Wot[HIDD*HIDD];
__device__ float g_Wf1t[HIDD*FFND];
__device__ float g_Wf2t[FFND*HIDD];

// ---------------- tf32 helpers ----------------
__device__ __forceinline__ float to_tf32(float x) {
    unsigned u;
    asm("cvt.rna.tf32.f32 %0, %1;" : "=r"(u) : "f"(x));
    return __uint_as_float(u);
}
__device__ __forceinline__ void mma_tf32(float* c, const unsigned* a, const unsigned* b) {
    asm volatile(
        "mma.sync.aligned.m16n8k8.row.col.f32.tf32.tf32.f32 "
        "{%0,%1,%2,%3},{%4,%5,%6,%7},{%8,%9},{%0,%1,%2,%3};"
        : "+f"(c[0]), "+f"(c[1]), "+f"(c[2]), "+f"(c[3])
        : "r"(a[0]), "r"(a[1]), "r"(a[2]), "r"(a[3]), "r"(b[0]), "r"(b[1]));
}
__device__ __forceinline__ void cpa16(unsigned s, const void* g) {
    asm volatile("cp.async.cg.shared.global [%0], [%1], 16;" :: "r"(s), "l"(g));
}

constexpr int LA = 36;   // A smem pitch -> conflict-free frag LDS
constexpr int LB = 72;   // B smem pitch -> conflict-free frag LDS
constexpr int ASZ = 64 * LA;
constexpr int BSZ = 32 * LB;
constexpr int GSMEM = 3 * (ASZ + BSZ) * (int)sizeof(float);   // 54 KB dynamic

// ---- pre-round all GEMM operands to tf32 (weights + x), 7 tensors --------
struct CvtArgs {
    const float* src[7];
    float*       dst[7];
    int          n4[7];   // element count / 4
};
__global__ __launch_bounds__(256) void cvt_kernel(CvtArgs a) {
    const int id = blockIdx.y;
    const float4* s = (const float4*)a.src[id];
    float4*       d = (float4*)a.dst[id];
    const int n4 = a.n4[id];
    const int stride = gridDim.x * blockDim.x;
    for (int i = blockIdx.x * blockDim.x + threadIdx.x; i < n4; i += stride) {
        float4 v = s[i];
        d[i] = make_float4(to_tf32(v.x), to_tf32(v.y), to_tf32(v.z), to_tf32(v.w));
    }
}

// ---------------- tf32 GEMM body: 64x64 tile, 256 threads ------------------
// cp.async 3-stage pipeline, no cvt in hot loop (operands pre-rounded).
// 8 warps (4M x 2N), warp tile 16x32, K-chunk 32, 1 sync per chunk.
template<bool RELU_RND>
__device__ __forceinline__ void gemm_body(
    const float* __restrict__ in, int lda,
    const float* __restrict__ W,
    const float* __restrict__ bias,
    float* __restrict__ out,
    int KTOT, int ldW, int r0, int cb0,
    float* As, float* Bs)
{
    const int tid  = threadIdx.x;
    const int warp = tid >> 5;
    const int lane = tid & 31;
    const int g    = lane >> 2;
    const int l    = lane & 3;
    const int wm   = warp & 3;
    const int wn   = warp >> 2;

    float c[4][4];
#pragma unroll
    for (int j = 0; j < 4; j++)
#pragma unroll
        for (int q = 0; q < 4; q++) c[j][q] = 0.f;

    const int am = tid >> 3, ac4 = tid & 7;     // A rows am, am+32; col group ac4
    const int bk = tid >> 4, bc4 = tid & 15;    // B rows bk, bk+16; col group bc4

    const unsigned uA = (unsigned)__cvta_generic_to_shared(As);
    const unsigned uB = (unsigned)__cvta_generic_to_shared(Bs);

    auto issue = [&](int ch) {
        const int st = ch % 3;
        const int kc = ch << 5;
        cpa16(uA + (unsigned)(st * ASZ + am * LA + ac4 * 4) * 4u,
              in + (size_t)(r0 + am) * lda + kc + ac4 * 4);
        cpa16(uA + (unsigned)(st * ASZ + (am + 32) * LA + ac4 * 4) * 4u,
              in + (size_t)(r0 + am + 32) * lda + kc + ac4 * 4);
        cpa16(uB + (unsigned)(st * BSZ + bk * LB + bc4 * 4) * 4u,
              W + (size_t)(kc + bk) * ldW + cb0 + bc4 * 4);
        cpa16(uB + (unsigned)(st * BSZ + (bk + 16) * LB + bc4 * 4) * 4u,
              W + (size_t)(kc + bk + 16) * ldW + cb0 + bc4 * 4);
        asm volatile("cp.async.commit_group;");
    };

    const int NC = KTOT >> 5;   // NC >= 4 for all our shapes
    issue(0);
    issue(1);

    for (int ch = 0; ch < NC; ch++) {
        asm volatile("cp.async.wait_group 1;");
        __syncthreads();
        const float* Ac = As + (ch % 3) * ASZ;
        const float* Bc = Bs + (ch % 3) * BSZ;
#pragma unroll
        for (int ks = 0; ks < 4; ks++) {
            const int k0 = ks * 8;
            unsigned a[4];
            const int ar = wm * 16 + g;
            a[0] = __float_as_uint(Ac[ar * LA + k0 + l]);
            a[1] = __float_as_uint(Ac[(ar + 8) * LA + k0 + l]);
            a[2] = __float_as_uint(Ac[ar * LA + k0 + l + 4]);
            a[3] = __float_as_uint(Ac[(ar + 8) * LA + k0 + l + 4]);
#pragma unroll
            for (int j = 0; j < 4; j++) {
                unsigned b[2];
                const int bc = wn * 32 + j * 8 + g;
                b[0] = __float_as_uint(Bc[(k0 + l) * LB + bc]);
                b[1] = __float_as_uint(Bc[(k0 + l + 4) * LB + bc]);
                mma_tf32(c[j], a, b);
            }
        }
        if (ch + 2 < NC) {
            issue(ch + 2);
        } else {
            asm volatile("cp.async.commit_group;");  // keep group count in lockstep
        }
    }

    const int row0 = r0 + wm * 16 + g;
#pragma unroll
    for (int j = 0; j < 4; j++) {
        const int col = cb0 + wn * 32 + j * 8 + l * 2;
        const float b0 = bias[col], b1 = bias[col + 1];
        float v00 = c[j][0] + b0, v01 = c[j][1] + b1;
        float v10 = c[j][2] + b0, v11 = c[j][3] + b1;
        if (RELU_RND) {   // f1: relu then round (output feeds f2's A operand)
            v00 = to_tf32(fmaxf(v00, 0.f)); v01 = to_tf32(fmaxf(v01, 0.f));
            v10 = to_tf32(fmaxf(v10, 0.f)); v11 = to_tf32(fmaxf(v11, 0.f));
        }
        *(float2*)&out[(size_t)row0 * ldW + col]       = make_float2(v00, v01);
        *(float2*)&out[(size_t)(row0 + 8) * ldW + col] = make_float2(v10, v11);
    }
}

template<bool RELU_RND>
__global__ __launch_bounds__(256) void gemm_tc(
    const float* __restrict__ in, const float* __restrict__ W,
    const float* __restrict__ bias, float* __restrict__ out,
    int KTOT, int ldW)
{
    extern __shared__ float smem[];
    gemm_body<RELU_RND>(in, KTOT, W, bias, out, KTOT, ldW,
                        blockIdx.x * 64, blockIdx.y * 64, smem, smem + 3 * ASZ);
}

// fused QKV: blockIdx.y in [0,12)
__global__ __launch_bounds__(256) void gemm_qkv(
    const float* __restrict__ x,
    const float* __restrict__ Wq, const float* __restrict__ bq, float* __restrict__ oq,
    const float* __restrict__ Wk, const float* __restrict__ bk, float* __restrict__ ok,
    const float* __restrict__ Wv, const float* __restrict__ bv, float* __restrict__ ov)
{
    extern __shared__ float smem[];
    const int sel = blockIdx.y >> 2;
    const float* W = (sel == 0) ? Wq : (sel == 1) ? Wk : Wv;
    const float* b = (sel == 0) ? bq : (sel == 1) ? bk : bv;
    float*       o = (sel == 0) ? oq : (sel == 1) ? ok : ov;
    gemm_body<false>(x, HIDD, W, b, o, HIDD, HIDD,
                     blockIdx.x * 64, (blockIdx.y & 3) * 64, smem, smem + 3 * ASZ);
}

// Wo, split-K=2: grid (48, 4, 2). K=128 per split, lda=HIDD.
__global__ __launch_bounds__(256) void gemm_wo(
    const float* __restrict__ in, const float* __restrict__ Wo,
    const float* __restrict__ zero,
    float* __restrict__ p0, float* __restrict__ p1)
{
    extern __shared__ float smem[];
    const int z = blockIdx.z;
    gemm_body<false>(in + z * (HIDD / 2), HIDD,
                     Wo + (size_t)z * (HIDD / 2) * HIDD,
                     zero, z ? p1 : p0, HIDD / 2, HIDD,
                     blockIdx.x * 64, blockIdx.y * 64, smem, smem + 3 * ASZ);
}

// FFN-down, split-K=4: grid (48, 4, 4). K=256 per split, lda=FFND.
__global__ __launch_bounds__(256) void gemm_f2(
    const float* __restrict__ ffn, const float* __restrict__ Wf2,
    const float* __restrict__ zero,
    float* __restrict__ p0, float* __restrict__ p1,
    float* __restrict__ p2, float* __restrict__ p3)
{
    extern __shared__ float smem[];
    const int z = blockIdx.z;
    float* p = (z == 0) ? p0 : (z == 1) ? p1 : (z == 2) ? p2 : p3;
    gemm_body<false>(ffn + z * (FFND / 4), FFND,
                     Wf2 + (size_t)z * (FFND / 4) * HIDD,
                     zero, p, FFND / 4, HIDD,
                     blockIdx.x * 64, blockIdx.y * 64, smem, smem + 3 * ASZ);
}

// ---------------- attention: warp per (node, head), fused edge bias -------
// output rounded to tf32 (feeds Wo's A operand)
__global__ __launch_bounds__(256) void attn2(
    const int*   __restrict__ neighbors,
    const float* __restrict__ ef,     // [E, 32]
    const float* __restrict__ We,     // [32, 8]
    const float* __restrict__ be,     // [8]
    const float* __restrict__ Q,
    const float* __restrict__ K,
    const float* __restrict__ V,
    float* __restrict__ outp)
{
    const int n = blockIdx.x;
    const int h = threadIdx.x >> 5;
    const int lane = threadIdx.x & 31;
    const int tid = threadIdx.x;
    const unsigned FULL = 0xffffffffu;

    __shared__ float efs[DEG][33];
    __shared__ float Wes[256];
    __shared__ int s_nbr[DEG];
    __shared__ unsigned s_keep;

    {
        const float* eb = ef + (size_t)n * DEG * EDIM;
#pragma unroll
        for (int i = 0; i < 2; i++) {
            int lin = tid + i * 256;
            efs[lin >> 5][lin & 31] = eb[lin];
        }
        Wes[tid] = We[tid];
    }
    if (h == 0) {
        int v = (lane < DEG) ? neighbors[n * DEG + lane] : -1;
        bool keep = (lane < DEG);
#pragma unroll
        for (int d2 = 1; d2 < DEG; d2++) {
            int other = __shfl_sync(FULL, v, d2);
            if (d2 > lane && other == v) keep = false;
        }
        unsigned km = __ballot_sync(FULL, keep && lane < DEG);
        if (lane < DEG) s_nbr[lane] = v;
        if (lane == 0) s_keep = km;
    }
    __syncthreads();

    const int nb_l = (lane < DEG) ? s_nbr[lane] : 0;
    const unsigned km = s_keep;
    const float q = Q[(size_t)n * HIDD + h * DH + lane];

    float bias = be[h];
    if (lane < DEG) {
#pragma unroll
        for (int k = 0; k < EDIM; k++)
            bias = fmaf(efs[lane][k], Wes[k * 8 + h], bias);
    }

    float kv[DEG];
#pragma unroll
    for (int d = 0; d < DEG; d++) {
        int s = __shfl_sync(FULL, nb_l, d);
        kv[d] = K[(size_t)s * HIDD + h * DH + lane];
    }
    float myscore = -1e30f;
#pragma unroll
    for (int d = 0; d < DEG; d++) {
        float p = q * kv[d];
#pragma unroll
        for (int o = 16; o; o >>= 1) p += __shfl_xor_sync(FULL, p, o);
        if (lane == d) myscore = p;
    }

    const bool keep = (lane < DEG) && ((km >> lane) & 1u);
    myscore = keep ? fmaf(myscore, 0.17677669529663687f, bias) : -1e30f;

    float m = myscore;
#pragma unroll
    for (int o = 16; o; o >>= 1) m = fmaxf(m, __shfl_xor_sync(FULL, m, o));
    float e = keep ? expf(myscore - m) : 0.f;
    float ssum = e;
#pragma unroll
    for (int o = 16; o; o >>= 1) ssum += __shfl_xor_sync(FULL, ssum, o);
    const float w = e / ssum;

    float vv[DEG];
#pragma unroll
    for (int d = 0; d < DEG; d++) {
        int s = __shfl_sync(FULL, nb_l, d);
        vv[d] = V[(size_t)s * HIDD + h * DH + lane];
    }
    float acc = 0.f;
#pragma unroll
    for (int d = 0; d < DEG; d++) {
        float wd = __shfl_sync(FULL, w, d);
        acc = fmaf(wd, vv[d], acc);
    }
    outp[(size_t)n * HIDD + h * DH + lane] = to_tf32(acc);
}

// ---- 2-partial reduce + bias + residual + LN; writes full h1 + rounded h1t
__global__ __launch_bounds__(256) void ln_res3_kernel(
    const float* __restrict__ y0, const float* __restrict__ y1,
    const float* __restrict__ bias2,
    const float* __restrict__ res,
    const float* __restrict__ lg, const float* __restrict__ lb,
    float* __restrict__ out, float* __restrict__ out_t)
{
    const int warp = threadIdx.x >> 5, lane = threadIdx.x & 31;
    const int row = blockIdx.x * 8 + warp;
    const size_t off = (size_t)row * HIDD;
    const float4* y0p = (const float4*)(y0 + off);
    const float4* y1p = (const float4*)(y1 + off);
    const float4* rp  = (const float4*)(res + off);
    const float4* b2p = (const float4*)bias2;

    float4 v0 = y0p[lane],      v1 = y0p[lane + 32];
    float4 u0 = y1p[lane],      u1 = y1p[lane + 32];
    float4 r0 = rp[lane],       r1 = rp[lane + 32];
    float4 c0 = b2p[lane],      c1 = b2p[lane + 32];
    v0.x += u0.x + r0.x + c0.x; v0.y += u0.y + r0.y + c0.y;
    v0.z += u0.z + r0.z + c0.z; v0.w += u0.w + r0.w + c0.w;
    v1.x += u1.x + r1.x + c1.x; v1.y += u1.y + r1.y + c1.y;
    v1.z += u1.z + r1.z + c1.z; v1.w += u1.w + r1.w + c1.w;

    float s  = v0.x + v0.y + v0.z + v0.w + v1.x + v1.y + v1.z + v1.w;
    float s2 = v0.x*v0.x + v0.y*v0.y + v0.z*v0.z + v0.w*v0.w
             + v1.x*v1.x + v1.y*v1.y + v1.z*v1.z + v1.w*v1.w;
#pragma unroll
    for (int o = 16; o; o >>= 1) {
        s  += __shfl_xor_sync(0xffffffffu, s,  o);
        s2 += __shfl_xor_sync(0xffffffffu, s2, o);
    }
    const float mu = s * (1.f / 256.f);
    const float var = fmaxf(s2 * (1.f / 256.f) - mu * mu, 0.f);
    const float rs = rsqrtf(var + 1e-5f);

    const float4* gp = (const float4*)lg;
    const float4* bp = (const float4*)lb;
    float4 g0 = gp[lane], g1 = gp[lane + 32];
    float4 b0 = bp[lane], b1 = bp[lane + 32];
    float4 o0, o1;
    o0.x = (v0.x - mu) * rs * g0.x + b0.x;  o0.y = (v0.y - mu) * rs * g0.y + b0.y;
    o0.z = (v0.z - mu) * rs * g0.z + b0.z;  o0.w = (v0.w - mu) * rs * g0.w + b0.w;
    o1.x = (v1.x - mu) * rs * g1.x + b1.x;  o1.y = (v1.y - mu) * rs * g1.y + b1.y;
    o1.z = (v1.z - mu) * rs * g1.z + b1.z;  o1.w = (v1.w - mu) * rs * g1.w + b1.w;
    ((float4*)(out + off))[lane]      = o0;
    ((float4*)(out + off))[lane + 32] = o1;
    ((float4*)(out_t + off))[lane] =
        make_float4(to_tf32(o0.x), to_tf32(o0.y), to_tf32(o0.z), to_tf32(o0.w));
    ((float4*)(out_t + off))[lane + 32] =
        make_float4(to_tf32(o1.x), to_tf32(o1.y), to_tf32(o1.z), to_tf32(o1.w));
}

// ---------------- 4-partial reduce + bias + residual + LayerNorm ----------
__global__ __launch_bounds__(256) void ln_res4_kernel(
    const float* __restrict__ y0, const float* __restrict__ y1,
    const float* __restrict__ y2, const float* __restrict__ y3,
    const float* __restrict__ bias2,
    const float* __restrict__ res,
    const float* __restrict__ lg, const float* __restrict__ lb,
    float* __restrict__ out)
{
    const int warp = threadIdx.x >> 5, lane = threadIdx.x & 31;
    const int row = blockIdx.x * 8 + warp;
    const size_t off = (size_t)row * HIDD;
    const float4* y0p = (const float4*)(y0 + off);
    const float4* y1p = (const float4*)(y1 + off);
    const float4* y2p = (const float4*)(y2 + off);
    const float4* y3p = (const float4*)(y3 + off);
    const float4* rp  = (const float4*)(res + off);
    const float4* b2p = (const float4*)bias2;

    float4 v0, v1;
    {
        float4 a0 = y0p[lane], a1 = y1p[lane], a2 = y2p[lane], a3 = y3p[lane];
        float4 r0 = rp[lane],  c0 = b2p[lane];
        v0.x = a0.x + a1.x + a2.x + a3.x + r0.x + c0.x;
        v0.y = a0.y + a1.y + a2.y + a3.y + r0.y + c0.y;
        v0.z = a0.z + a1.z + a2.z + a3.z + r0.z + c0.z;
        v0.w = a0.w + a1.w + a2.w + a3.w + r0.w + c0.w;
    }
    {
        float4 a0 = y0p[lane+32], a1 = y1p[lane+32], a2 = y2p[lane+32], a3 = y3p[lane+32];
        float4 r1 = rp[lane+32],  c1 = b2p[lane+32];
        v1.x = a0.x + a1.x + a2.x + a3.x + r1.x + c1.x;
        v1.y = a0.y + a1.y + a2.y + a3.y + r1.y + c1.y;
        v1.z = a0.z + a1.z + a2.z + a3.z + r1.z + c1.z;
        v1.w = a0.w + a1.w + a2.w + a3.w + r1.w + c1.w;
    }

    float s  = v0.x + v0.y + v0.z + v0.w + v1.x + v1.y + v1.z + v1.w;
    float s2 = v0.x*v0.x + v0.y*v0.y + v0.z*v0.z + v0.w*v0.w
             + v1.x*v1.x + v1.y*v1.y + v1.z*v1.z + v1.w*v1.w;
#pragma unroll
    for (int o = 16; o; o >>= 1) {
        s  += __shfl_xor_sync(0xffffffffu, s,  o);
        s2 += __shfl_xor_sync(0xffffffffu, s2, o);
    }
    const float mu = s * (1.f / 256.f);
    const float var = fmaxf(s2 * (1.f / 256.f) - mu * mu, 0.f);
    const float rs = rsqrtf(var + 1e-5f);

    const float4* gp = (const float4*)lg;
    const float4* bp = (const float4*)lb;
    float4 g0 = gp[lane], g1 = gp[lane + 32];
    float4 b0 = bp[lane], b1 = bp[lane + 32];
    float4 o0, o1;
    o0.x = (v0.x - mu) * rs * g0.x + b0.x;  o0.y = (v0.y - mu) * rs * g0.y + b0.y;
    o0.z = (v0.z - mu) * rs * g0.z + b0.z;  o0.w = (v0.w - mu) * rs * g0.w + b0.w;
    o1.x = (v1.x - mu) * rs * g1.x + b1.x;  o1.y = (v1.y - mu) * rs * g1.y + b1.y;
    o1.z = (v1.z - mu) * rs * g1.z + b1.z;  o1.w = (v1.w - mu) * rs * g1.w + b1.w;
    ((float4*)(out + off))[lane]      = o0;
    ((float4*)(out + off))[lane + 32] = o1;
}

// ---------------- launch ----------------
extern "C" void kernel_launch(void* const* d_in, const int* in_sizes, int n_in,
                              void* d_out, int out_size)
{
    const float* x    = (const float*)d_in[0];
    const int*   nb   = (const int*)  d_in[1];
    const float* ef   = (const float*)d_in[2];
    const float* Wq   = (const float*)d_in[3];
    const float* bq   = (const float*)d_in[4];
    const float* Wk   = (const float*)d_in[5];
    const float* bk   = (const float*)d_in[6];
    const float* Wv   = (const float*)d_in[7];
    const float* bv   = (const float*)d_in[8];
    const float* We   = (const float*)d_in[9];
    const float* be   = (const float*)d_in[10];
    const float* Wo   = (const float*)d_in[11];
    const float* bo   = (const float*)d_in[12];
    const float* ln1g = (const float*)d_in[13];
    const float* ln1b = (const float*)d_in[14];
    const float* ln2g = (const float*)d_in[15];
    const float* ln2b = (const float*)d_in[16];
    const float* Wf1  = (const float*)d_in[17];
    const float* bf1  = (const float*)d_in[18];
    const float* Wf2  = (const float*)d_in[19];
    const float* bf2  = (const float*)d_in[20];
    float* out = (float*)d_out;

    float *pQ, *pK, *pV, *pA, *pH1, *pH1t, *pF, *pZ;
    float *pXt, *pWqt, *pWkt, *pWvt, *pWot, *pWf1t, *pWf2t;
    cudaGetSymbolAddress((void**)&pQ,   g_Q);
    cudaGetSymbolAddress((void**)&pK,   g_K);
    cudaGetSymbolAddress((void**)&pV,   g_V);
    cudaGetSymbolAddress((void**)&pA,   g_attn);
    cudaGetSymbolAddress((void**)&pH1,  g_h1);
    cudaGetSymbolAddress((void**)&pH1t, g_h1t);
    cudaGetSymbolAddress((void**)&pF,   g_ffn);
    cudaGetSymbolAddress((void**)&pZ,   g_zero);
    cudaGetSymbolAddress((void**)&pXt,  g_xt);
    cudaGetSymbolAddress((void**)&pWqt, g_Wqt);
    cudaGetSymbolAddress((void**)&pWkt, g_Wkt);
    cudaGetSymbolAddress((void**)&pWvt, g_Wvt);
    cudaGetSymbolAddress((void**)&pWot, g_Wot);
    cudaGetSymbolAddress((void**)&pWf1t, g_Wf1t);
    cudaGetSymbolAddress((void**)&pWf2t, g_Wf2t);

    // opt-in to 54 KB dynamic smem for the GEMM kernels (idempotent, capture-safe)
    cudaFuncSetAttribute(gemm_qkv,     cudaFuncAttributeMaxDynamicSharedMemorySize, GSMEM);
    cudaFuncSetAttribute(gemm_wo,      cudaFuncAttributeMaxDynamicSharedMemorySize, GSMEM);
    cudaFuncSetAttribute(gemm_f2,      cudaFuncAttributeMaxDynamicSharedMemorySize, GSMEM);
    cudaFuncSetAttribute(gemm_tc<true>,  cudaFuncAttributeMaxDynamicSharedMemorySize, GSMEM);

    // pre-round all GEMM operands to tf32
    CvtArgs ca;
    ca.src[0] = x;   ca.dst[0] = pXt;   ca.n4[0] = NN * HIDD / 4;
    ca.src[1] = Wq;  ca.dst[1] = pWqt;  ca.n4[1] = HIDD * HIDD / 4;
    ca.src[2] = Wk;  ca.dst[2] = pWkt;  ca.n4[2] = HIDD * HIDD / 4;
    ca.src[3] = Wv;  ca.dst[3] = pWvt;  ca.n4[3] = HIDD * HIDD / 4;
    ca.src[4] = Wo;  ca.dst[4] = pWot;  ca.n4[4] = HIDD * HIDD / 4;
    ca.src[5] = Wf1; ca.dst[5] = pWf1t; ca.n4[5] = HIDD * FFND / 4;
    ca.src[6] = Wf2; ca.dst[6] = pWf2t; ca.n4[6] = FFND * HIDD / 4;
    cvt_kernel<<<dim3(64, 7), 256>>>(ca);

    // fused QKV projection
    gemm_qkv<<<dim3(NN / 64, 12), 256, GSMEM>>>(pXt, pWqt, bq, pQ, pWkt, bk, pK, pWvt, bv, pV);

    // sparse attention with fused edge-bias projection (output tf32-rounded)
    attn2<<<NN, 256>>>(nb, ef, We, be, pQ, pK, pV, pA);

    // Wo split-K=2 -> partials pQ, pK; reduce + bo + residual(x) + LN1 -> h1, h1t
    gemm_wo<<<dim3(NN / 64, HIDD / 64, 2), 256, GSMEM>>>(pA, pWot, pZ, pQ, pK);
    ln_res3_kernel<<<NN / 8, 256>>>(pQ, pK, bo, x, ln1g, ln1b, pH1, pH1t);

    // FFN up + ReLU (output tf32-rounded)
    gemm_tc<true><<<dim3(NN / 64, FFND / 64), 256, GSMEM>>>(pH1t, pWf1t, bf1, pF, HIDD, FFND);

    // FFN down split-K=4 -> partials pQ,pK,pV,pA; reduce + bf2 + res(h1) + LN2
    gemm_f2<<<dim3(NN / 64, HIDD / 64, 4), 256, GSMEM>>>(pF, pWf2t, pZ, pQ, pK, pV, pA);
    ln_res4_kernel<<<NN / 8, 256>>>(pQ, pK, pV, pA, bf2, pH1, ln2g, ln2b, out);
}